// round 3
// baseline (speedup 1.0000x reference)
#include <cuda_runtime.h>
#include <cstddef>

// RNN_22883585753135: 2-layer tanh RNN, B=64, T=4096, IN=H=128
//   out = concat( out1[B,T,H], h_n[2,B,H] )
//
// Round 3: fused pipelined recurrence.
//   1. gemm_xw:  xp0 = x @ W_ih0^T + (b_ih0+b_hh0)          -> g_xp
//   2. fused_rec: one CTA per batch row, 3 warp-groups:
//        A: layer-0 scan        (h0_s)
//        B: layer-1 input proj  (z1_{s-1} = W_ih1 h0_{s-1} + b)  [replaces GEMM #2]
//        C: layer-1 scan        (h1_{s-2}) -> out1, lagging 2 supersteps
//      T+2 supersteps total instead of 2T sequential steps.

typedef unsigned long long ull;

#define BB 64
#define TT 4096
#define HH 128
#define BT (BB * TT)
#define PF 4            // xp prefetch ring depth

// Scratch (allocation-free rule): padded so the prefetch ring can overrun.
__device__ __align__(16) float g_xp[(size_t)(BT + PF) * HH];

// ---------------- packed f32x2 helpers (sm_100+) ----------------
__device__ __forceinline__ ull fma2(ull a, ull b, ull c) {
    ull d;
    asm("fma.rn.f32x2 %0, %1, %2, %3;" : "=l"(d) : "l"(a), "l"(b), "l"(c));
    return d;
}
__device__ __forceinline__ ull add2(ull a, ull b) {
    ull d;
    asm("add.rn.f32x2 %0, %1, %2;" : "=l"(d) : "l"(a), "l"(b));
    return d;
}
__device__ __forceinline__ float2 unpack2(ull v) {
    float2 f;
    asm("mov.b64 {%0, %1}, %2;" : "=f"(f.x), "=f"(f.y) : "l"(v));
    return f;
}

// Accurate tanh (~1e-7 rel)
__device__ __forceinline__ float tanh_fast(float x) {
    float ax = fminf(fabsf(x), 15.0f);
    float e  = __expf(2.0f * ax);
    float r  = __fdividef(e - 1.0f, e + 1.0f);
    return copysignf(r, x);
}

// dot of register-resident 128-wide row with a 16B-aligned smem vector
__device__ __forceinline__ float dot128(const ull* w, const float* hbuf) {
    const ulonglong2* hv = (const ulonglong2*)hbuf;
    ull a0 = 0ull, a1 = 0ull, a2 = 0ull, a3 = 0ull;
    #pragma unroll
    for (int k = 0; k < 32; k += 2) {
        ulonglong2 h01 = hv[k];
        ulonglong2 h23 = hv[k + 1];
        a0 = fma2(h01.x, w[2 * k],     a0);
        a1 = fma2(h01.y, w[2 * k + 1], a1);
        a2 = fma2(h23.x, w[2 * k + 2], a2);
        a3 = fma2(h23.y, w[2 * k + 3], a3);
    }
    float2 v = unpack2(add2(add2(a0, a2), add2(a1, a3)));
    return v.x + v.y;
}

// ---------------- GEMM: out[m][n] = sum_k A[m,k]*W[n,k] + b0[n]+b1[n] ----
#define AS_STRIDE 66
#define WS_STRIDE 130
#define GEMM_SMEM_ULL (64 * AS_STRIDE + 64 * WS_STRIDE)
#define GEMM_SMEM_BYTES (GEMM_SMEM_ULL * 8)

__global__ void __launch_bounds__(256, 1) gemm_xw(
    const float* __restrict__ A, const float* __restrict__ W,
    const float* __restrict__ b0, const float* __restrict__ b1,
    float* __restrict__ out)
{
    extern __shared__ ull sm[];
    ull* As = sm;
    ull* Ws = sm + 64 * AS_STRIDE;

    const int tid = threadIdx.x;
    const size_t m0 = (size_t)blockIdx.x * 64;

    const ull* Ag = (const ull*)(A + m0 * HH);
    #pragma unroll
    for (int i = 0; i < 16; i++) {
        int idx = tid + i * 256;
        int r = idx >> 6, k2 = idx & 63;
        As[k2 * AS_STRIDE + r] = Ag[(size_t)r * 64 + k2];
    }
    const ull* Wg = (const ull*)W;
    #pragma unroll
    for (int i = 0; i < 32; i++) {
        int idx = tid + i * 256;
        int n = idx >> 6, k2 = idx & 63;
        Ws[k2 * WS_STRIDE + n] = Wg[n * 64 + k2];
    }
    __syncthreads();

    const int tx = tid & 15;
    const int ty = tid >> 4;
    ull acc[4][8];
    #pragma unroll
    for (int r = 0; r < 4; r++)
        #pragma unroll
        for (int c = 0; c < 8; c++) acc[r][c] = 0ull;

    #pragma unroll 4
    for (int k2 = 0; k2 < 64; k2++) {
        ull a2[4], w2[8];
        #pragma unroll
        for (int r = 0; r < 4; r++) a2[r] = As[k2 * AS_STRIDE + ty * 4 + r];
        #pragma unroll
        for (int c = 0; c < 8; c++) w2[c] = Ws[k2 * WS_STRIDE + tx + 16 * c];
        #pragma unroll
        for (int r = 0; r < 4; r++)
            #pragma unroll
            for (int c = 0; c < 8; c++)
                acc[r][c] = fma2(a2[r], w2[c], acc[r][c]);
    }

    float bias[8];
    #pragma unroll
    for (int c = 0; c < 8; c++) {
        int n = tx + 16 * c;
        bias[c] = __ldg(b0 + n) + __ldg(b1 + n);
    }
    #pragma unroll
    for (int r = 0; r < 4; r++) {
        size_t row = m0 + ty * 4 + r;
        #pragma unroll
        for (int c = 0; c < 8; c++) {
            float2 v = unpack2(acc[r][c]);
            out[row * HH + tx + 16 * c] = v.x + v.y + bias[c];
        }
    }
}

// ---------------- Fused pipelined recurrence ----------------
// 64 CTAs (one per batch row) x 384 threads (3 groups of 128).
// Superstep s: A computes h0_s, B computes z1_{s-1}, C computes h1_{s-2}.
// All reads hit parity (s&1) written at s-1; all writes go to parity (s&1)^1
// in DIFFERENT arrays -> one __syncthreads per superstep.

__global__ void __launch_bounds__(384, 1) fused_rec(
    const float* __restrict__ xp0,
    const float* __restrict__ Whh0, const float* __restrict__ Wih1,
    const float* __restrict__ bih1, const float* __restrict__ bhh1,
    const float* __restrict__ Whh1,
    float* __restrict__ out1, float* __restrict__ hN)
{
    const int b     = blockIdx.x;
    const int tid   = threadIdx.x;
    const int group = tid >> 7;      // 0=A, 1=B, 2=C
    const int j     = tid & 127;

    __shared__ __align__(16) float h0s[2][HH];
    __shared__ __align__(16) float h1s[2][HH];
    __shared__ __align__(16) float z1s[2][HH];

    // per-group weight row -> 64 packed f32x2 registers
    const float* wsrc = (group == 0) ? (Whh0 + j * HH)
                      : (group == 1) ? (Wih1 + j * HH)
                                     : (Whh1 + j * HH);
    ull w[64];
    const ull* wg = (const ull*)wsrc;
    #pragma unroll
    for (int i = 0; i < 64; i++) w[i] = wg[i];

    float bias1 = 0.0f;
    if (group == 1) bias1 = __ldg(bih1 + j) + __ldg(bhh1 + j);

    if (group == 0) { h0s[0][j] = 0.0f; h0s[1][j] = 0.0f; }
    if (group == 2) { h1s[0][j] = 0.0f; h1s[1][j] = 0.0f; }
    if (group == 1) { z1s[0][j] = 0.0f; z1s[1][j] = 0.0f; }

    const float* p  = xp0  + (size_t)b * TT * HH + j;   // group A stream
    float*       po = out1 + (size_t)b * TT * HH + j;   // group C stream

    float xr[PF];
    if (group == 0) {
        #pragma unroll
        for (int i = 0; i < PF; i++) xr[i] = __ldg(p + (size_t)i * HH);
    }
    __syncthreads();

    #pragma unroll 2
    for (int s = 0; s < TT; s++) {
        const int rp = s & 1;
        if (group == 0) {
            float xv = xr[0];
            #pragma unroll
            for (int i = 0; i < PF - 1; i++) xr[i] = xr[i + 1];
            xr[PF - 1] = __ldg(p + (size_t)(s + PF) * HH);   // padded, safe
            float hn = tanh_fast(dot128(w, h0s[rp]) + xv);
            h0s[rp ^ 1][j] = hn;
        } else if (group == 1) {
            z1s[rp ^ 1][j] = dot128(w, h0s[rp]) + bias1;
        } else if (s >= 2) {
            float hn = tanh_fast(dot128(w, h1s[rp]) + z1s[rp][j]);
            h1s[rp ^ 1][j] = hn;
            po[(size_t)(s - 2) * HH] = hn;
        }
        __syncthreads();
    }

    // epilogue superstep s = TT (rp=0): B -> z1_{T-1}, C -> h1_{T-2}
    if (group == 1) {
        z1s[1][j] = dot128(w, h0s[0]) + bias1;
    } else if (group == 2) {
        float hn = tanh_fast(dot128(w, h1s[0]) + z1s[0][j]);
        h1s[1][j] = hn;
        po[(size_t)(TT - 2) * HH] = hn;
    }
    __syncthreads();

    // epilogue superstep s = TT+1 (rp=1): C -> h1_{T-1}
    if (group == 2) {
        float hn = tanh_fast(dot128(w, h1s[1]) + z1s[1][j]);
        h1s[0][j] = hn;
        po[(size_t)(TT - 1) * HH] = hn;
    }
    __syncthreads();

    // final hidden states: h0_{T-1} is in h0s[0] (written at s=T-1, untouched
    // after), h1_{T-1} is in h1s[0].
    if (group == 0) hN[b * HH + j] = h0s[0][j];
    if (group == 2) hN[BB * HH + b * HH + j] = h1s[0][j];
}

// ---------------- launch ----------------
extern "C" void kernel_launch(void* const* d_in, const int* in_sizes, int n_in,
                              void* d_out, int out_size)
{
    const float* x     = (const float*)d_in[0];
    const float* W_ih0 = (const float*)d_in[1];
    const float* W_hh0 = (const float*)d_in[2];
    const float* b_ih0 = (const float*)d_in[3];
    const float* b_hh0 = (const float*)d_in[4];
    const float* W_ih1 = (const float*)d_in[5];
    const float* W_hh1 = (const float*)d_in[6];
    const float* b_ih1 = (const float*)d_in[7];
    const float* b_hh1 = (const float*)d_in[8];

    float* out1 = (float*)d_out;                 // [B,T,H]
    float* hN   = out1 + (size_t)BT * HH;        // [2,B,H]

    void* xp_p = nullptr;
    cudaGetSymbolAddress(&xp_p, g_xp);
    float* xp = (float*)xp_p;

    static int smem_set = 0;
    if (!smem_set) {
        cudaFuncSetAttribute(gemm_xw,
                             cudaFuncAttributeMaxDynamicSharedMemorySize,
                             GEMM_SMEM_BYTES);
        smem_set = 1;
    }

    gemm_xw<<<BT / 64, 256, GEMM_SMEM_BYTES>>>(x, W_ih0, b_ih0, b_hh0, xp);
    fused_rec<<<BB, 384>>>(xp, W_hh0, W_ih1, b_ih1, b_hh1, W_hh1, out1, hN);
}

// round 4
// speedup vs baseline: 1.3689x; 1.3689x over previous
#include <cuda_runtime.h>
#include <cstddef>

// RNN_22883585753135: 2-layer tanh RNN, B=64, T=4096, IN=H=128
//   out = concat( out1[B,T,H], h_n[2,B,H] )
//
// Round 4: fully fused, cross-CTA pipelined. No GEMM kernels at all.
//   128 CTAs x 256 threads:
//     blocks 0..63   (producer, batch b): proj grp: z0=Wih0*x+b ; rec grp: h0
//         h0 stream -> g_h0 + watermark flag (release) every CHUNK steps
//     blocks 64..127 (consumer, batch b): proj grp: z1=Wih1*h0+b ; rec grp: h1
//         h0 stream read from g_h0, gated by acquire-polled watermark
//   Per CTA: one __syncthreads per superstep; parity double-buffers.
//   255-reg budget at 256 thr keeps the 128-reg weight rows spill-free
//   (round-3 regression root cause: 384 thr -> 168-reg cap -> spills).

typedef unsigned long long ull;

#define BB 64
#define TT 4096
#define HH 128
#define BT (BB * TT)
#define PF 4            // input-vector prefetch ring depth
#define CHUNK 32        // watermark granularity (steps)
#define H0STRIDE (TT + 8)   // rows per batch in g_h0 (pad for ring overrun)

// Scratch (allocation-free rule)
__device__ __align__(16) float g_h0[(size_t)BB * H0STRIDE * HH];
__device__ int g_flag[BB];

// ---------------- packed f32x2 helpers (sm_100+) ----------------
__device__ __forceinline__ ull fma2(ull a, ull b, ull c) {
    ull d;
    asm("fma.rn.f32x2 %0, %1, %2, %3;" : "=l"(d) : "l"(a), "l"(b), "l"(c));
    return d;
}
__device__ __forceinline__ ull add2(ull a, ull b) {
    ull d;
    asm("add.rn.f32x2 %0, %1, %2;" : "=l"(d) : "l"(a), "l"(b));
    return d;
}
__device__ __forceinline__ float2 unpack2(ull v) {
    float2 f;
    asm("mov.b64 {%0, %1}, %2;" : "=f"(f.x), "=f"(f.y) : "l"(v));
    return f;
}

__device__ __forceinline__ int ld_acquire(const int* p) {
    int v;
    asm volatile("ld.acquire.gpu.b32 %0, [%1];" : "=r"(v) : "l"(p) : "memory");
    return v;
}
__device__ __forceinline__ void st_release(int* p, int v) {
    asm volatile("st.release.gpu.b32 [%0], %1;" :: "l"(p), "r"(v) : "memory");
}

// tanh(x) = 1 - 2/(e^{2x}+1); branch-free, correct limits at +-inf, ~1e-7 rel
__device__ __forceinline__ float tanh_acc(float x) {
    float e = __expf(2.0f * x);
    return 1.0f - __fdividef(2.0f, e + 1.0f);
}

// 128-wide dot: register row (64 packed f32x2) x smem vector; 8 accumulator
// chains -> dependent depth 8 FFMA2 (32 cyc) instead of 16.
__device__ __forceinline__ float dot128_8(const ull* w, const float* hbuf) {
    const ulonglong2* hv = (const ulonglong2*)hbuf;
    ull a0=0ull,a1=0ull,a2=0ull,a3=0ull,a4=0ull,a5=0ull,a6=0ull,a7=0ull;
    #pragma unroll
    for (int k = 0; k < 32; k += 4) {
        ulonglong2 h01 = hv[k];
        ulonglong2 h23 = hv[k + 1];
        ulonglong2 h45 = hv[k + 2];
        ulonglong2 h67 = hv[k + 3];
        a0 = fma2(h01.x, w[2*k+0], a0);
        a1 = fma2(h01.y, w[2*k+1], a1);
        a2 = fma2(h23.x, w[2*k+2], a2);
        a3 = fma2(h23.y, w[2*k+3], a3);
        a4 = fma2(h45.x, w[2*k+4], a4);
        a5 = fma2(h45.y, w[2*k+5], a5);
        a6 = fma2(h67.x, w[2*k+6], a6);
        a7 = fma2(h67.y, w[2*k+7], a7);
    }
    ull s0 = add2(a0, a4), s1 = add2(a1, a5);
    ull s2 = add2(a2, a6), s3 = add2(a3, a7);
    float2 v = unpack2(add2(add2(s0, s2), add2(s1, s3)));
    return v.x + v.y;
}

// ---------------- flag reset (runs first each launch/replay) ----------------
__global__ void flag_init() {
    if (threadIdx.x < BB) g_flag[threadIdx.x] = 0;
}

// ---------------- fused pipelined RNN ----------------
__global__ void __launch_bounds__(256, 1) rnn_fused(
    const float* __restrict__ x,
    const float* __restrict__ Wih0, const float* __restrict__ Whh0,
    const float* __restrict__ bih0, const float* __restrict__ bhh0,
    const float* __restrict__ Wih1, const float* __restrict__ Whh1,
    const float* __restrict__ bih1, const float* __restrict__ bhh1,
    float* __restrict__ out1, float* __restrict__ hN)
{
    const int role = blockIdx.x >> 6;      // 0 = layer0 (producer), 1 = layer1
    const int b    = blockIdx.x & 63;
    const int tid  = threadIdx.x;
    const int grp  = tid >> 7;             // 0 = proj, 1 = rec
    const int j    = tid & 127;

    __shared__ __align__(16) float vs[2][HH];  // staged input vector (x or h0)
    __shared__ __align__(16) float zs[2][HH];  // z = Wih*v + bias
    __shared__ __align__(16) float hs[2][HH];  // recurrent state

    // weight row -> 64 packed f32x2 registers
    const float* wsrc = (role == 0) ? (grp == 0 ? Wih0 : Whh0)
                                    : (grp == 0 ? Wih1 : Whh1);
    ull w[64];
    {
        const ull* wg = (const ull*)(wsrc + (size_t)j * HH);
        #pragma unroll
        for (int i = 0; i < 64; i++) w[i] = wg[i];
    }

    float bias = 0.0f;
    if (grp == 0)
        bias = (role == 0) ? (__ldg(bih0 + j) + __ldg(bhh0 + j))
                           : (__ldg(bih1 + j) + __ldg(bhh1 + j));

    const float* vstream = (role == 0)
        ? x    + (size_t)b * TT * HH
        : g_h0 + (size_t)b * H0STRIDE * HH;
    float* hout = (role == 0)
        ? g_h0 + (size_t)b * H0STRIDE * HH
        : out1 + (size_t)b * TT * HH;
    int* flagp = &g_flag[b];

    if (grp == 0) { zs[0][j] = 0.0f; zs[1][j] = 0.0f; }
    else          { hs[0][j] = 0.0f; hs[1][j] = 0.0f; }
    __syncthreads();

    float ring[PF];

    for (int c = 0; c < TT / CHUNK; c++) {
        const int s0 = c * CHUNK;

        if (role == 1) {           // gate this chunk's h0 reads (incl. ring)
            if (tid == 0) {
                const int need = s0 + CHUNK + PF + 1;
                while (ld_acquire(flagp) < need) __nanosleep(64);
            }
            __syncthreads();
        }
        if (c == 0) {              // prologue after gate: stage v[0], prime ring
            if (grp == 0) {
                vs[0][j] = __ldg(vstream + j);
                #pragma unroll
                for (int i = 0; i < PF; i++)
                    ring[i] = __ldg(vstream + (size_t)(1 + i) * HH + j);
            }
            __syncthreads();
        }

        #pragma unroll 2
        for (int sl = 0; sl < CHUNK; sl++) {
            const int s = s0 + sl;
            const int p = s & 1;
            if (grp == 0) {
                float vnext = ring[0];
                #pragma unroll
                for (int i = 0; i < PF - 1; i++) ring[i] = ring[i + 1];
                int pr = s + 1 + PF;
                if (role == 0 && pr > TT - 1) pr = TT - 1;  // never read past x
                ring[PF - 1] = __ldg(vstream + (size_t)pr * HH + j);

                zs[p ^ 1][j] = dot128_8(w, vs[p]) + bias;   // z for time s
                vs[p ^ 1][j] = vnext;                       // stage v[s+1]
            } else if (s > 0) {
                // h[s-1] = tanh(z[s-1] + Whh * h[s-2])
                float hn = tanh_acc(dot128_8(w, hs[p]) + zs[p][j]);
                hs[p ^ 1][j] = hn;
                hout[(size_t)(s - 1) * HH + j] = hn;
            }
            __syncthreads();
        }

        if (role == 0) {           // publish watermark: rows 0..s0+CHUNK-2 done
            __threadfence();
            __syncthreads();
            if (tid == 0) st_release(flagp, s0 + CHUNK - 1);
        }
    }

    // epilogue step s = TT (parity 0): rec computes h[TT-1]
    float hfin = 0.0f;
    if (grp == 1) {
        hfin = tanh_acc(dot128_8(w, hs[0]) + zs[0][j]);
        hout[(size_t)(TT - 1) * HH + j] = hfin;
    }
    if (role == 0) {               // sentinel: everything (incl. row TT-1) done
        __threadfence();
        __syncthreads();
        if (tid == 0) st_release(flagp, TT + CHUNK + PF + 2);
    }
    if (grp == 1)
        hN[(size_t)role * BB * HH + (size_t)b * HH + j] = hfin;
}

// ---------------- launch ----------------
extern "C" void kernel_launch(void* const* d_in, const int* in_sizes, int n_in,
                              void* d_out, int out_size)
{
    const float* x     = (const float*)d_in[0];
    const float* W_ih0 = (const float*)d_in[1];
    const float* W_hh0 = (const float*)d_in[2];
    const float* b_ih0 = (const float*)d_in[3];
    const float* b_hh0 = (const float*)d_in[4];
    const float* W_ih1 = (const float*)d_in[5];
    const float* W_hh1 = (const float*)d_in[6];
    const float* b_ih1 = (const float*)d_in[7];
    const float* b_hh1 = (const float*)d_in[8];

    float* out1 = (float*)d_out;                 // [B,T,H]
    float* hN   = out1 + (size_t)BT * HH;        // [2,B,H]

    flag_init<<<1, 64>>>();
    rnn_fused<<<2 * BB, 256>>>(x, W_ih0, W_hh0, b_ih0, b_hh0,
                               W_ih1, W_hh1, b_ih1, b_hh1, out1, hN);
}